// round 1
// baseline (speedup 1.0000x reference)
#include <cuda_runtime.h>
#include <math.h>

#define B_   2
#define N_   6
#define C_   80
#define FH_  16
#define FW_  44
#define D_   112
#define NX_  128
#define NY_  128
#define BN_  (B_*N_)
#define PIX_ (FH_*FW_)          // 704
#define NPIX_ (BN_*PIX_)        // 8448
#define OUTN_ (B_*C_*NX_*NY_)   // 2621440

__device__ float g_comb[BN_][16];    // bda @ s2e @ inv(intrin)
__device__ float g_idainv[BN_][16];  // inv(ida)

// ---------------------------------------------------------------------------
// general 4x4 inverse (adjugate, double precision)
// ---------------------------------------------------------------------------
__device__ void inv4x4d(const float* src, double* out) {
    double m[16];
    #pragma unroll
    for (int i = 0; i < 16; i++) m[i] = (double)src[i];
    double inv[16];
    inv[0]  =  m[5]*m[10]*m[15] - m[5]*m[11]*m[14] - m[9]*m[6]*m[15] + m[9]*m[7]*m[14] + m[13]*m[6]*m[11] - m[13]*m[7]*m[10];
    inv[4]  = -m[4]*m[10]*m[15] + m[4]*m[11]*m[14] + m[8]*m[6]*m[15] - m[8]*m[7]*m[14] - m[12]*m[6]*m[11] + m[12]*m[7]*m[10];
    inv[8]  =  m[4]*m[9]*m[15]  - m[4]*m[11]*m[13] - m[8]*m[5]*m[15] + m[8]*m[7]*m[13] + m[12]*m[5]*m[11] - m[12]*m[7]*m[9];
    inv[12] = -m[4]*m[9]*m[14]  + m[4]*m[10]*m[13] + m[8]*m[5]*m[14] - m[8]*m[6]*m[13] - m[12]*m[5]*m[10] + m[12]*m[6]*m[9];
    inv[1]  = -m[1]*m[10]*m[15] + m[1]*m[11]*m[14] + m[9]*m[2]*m[15] - m[9]*m[3]*m[14] - m[13]*m[2]*m[11] + m[13]*m[3]*m[10];
    inv[5]  =  m[0]*m[10]*m[15] - m[0]*m[11]*m[14] - m[8]*m[2]*m[15] + m[8]*m[3]*m[14] + m[12]*m[2]*m[11] - m[12]*m[3]*m[10];
    inv[9]  = -m[0]*m[9]*m[15]  + m[0]*m[11]*m[13] + m[8]*m[1]*m[15] - m[8]*m[3]*m[13] - m[12]*m[1]*m[11] + m[12]*m[3]*m[9];
    inv[13] =  m[0]*m[9]*m[14]  - m[0]*m[10]*m[13] - m[8]*m[1]*m[14] + m[8]*m[2]*m[13] + m[12]*m[1]*m[10] - m[12]*m[2]*m[9];
    inv[2]  =  m[1]*m[6]*m[15]  - m[1]*m[7]*m[14]  - m[5]*m[2]*m[15] + m[5]*m[3]*m[14] + m[13]*m[2]*m[7]  - m[13]*m[3]*m[6];
    inv[6]  = -m[0]*m[6]*m[15]  + m[0]*m[7]*m[14]  + m[4]*m[2]*m[15] - m[4]*m[3]*m[14] - m[12]*m[2]*m[7]  + m[12]*m[3]*m[6];
    inv[10] =  m[0]*m[5]*m[15]  - m[0]*m[7]*m[13]  - m[4]*m[1]*m[15] + m[4]*m[3]*m[13] + m[12]*m[1]*m[7]  - m[12]*m[3]*m[5];
    inv[14] = -m[0]*m[5]*m[14]  + m[0]*m[6]*m[13]  + m[4]*m[1]*m[14] - m[4]*m[2]*m[13] - m[12]*m[1]*m[6]  + m[12]*m[2]*m[5];
    inv[3]  = -m[1]*m[6]*m[11]  + m[1]*m[7]*m[10]  + m[5]*m[2]*m[11] - m[5]*m[3]*m[10] - m[9]*m[2]*m[7]   + m[9]*m[3]*m[6];
    inv[7]  =  m[0]*m[6]*m[11]  - m[0]*m[7]*m[10]  - m[4]*m[2]*m[11] + m[4]*m[3]*m[10] + m[8]*m[2]*m[7]   - m[8]*m[3]*m[6];
    inv[11] = -m[0]*m[5]*m[11]  + m[0]*m[7]*m[9]   + m[4]*m[1]*m[11] - m[4]*m[3]*m[9]  - m[8]*m[1]*m[7]   + m[8]*m[3]*m[5];
    inv[15] =  m[0]*m[5]*m[10]  - m[0]*m[6]*m[9]   - m[4]*m[1]*m[10] + m[4]*m[2]*m[9]  + m[8]*m[1]*m[6]   - m[8]*m[2]*m[5];
    double det = m[0]*inv[0] + m[1]*inv[4] + m[2]*inv[8] + m[3]*inv[12];
    det = 1.0 / det;
    #pragma unroll
    for (int i = 0; i < 16; i++) out[i] = inv[i] * det;
}

__device__ void mm4d(const double* A, const double* Bm, double* Cm) {
    #pragma unroll
    for (int i = 0; i < 4; i++)
        #pragma unroll
        for (int j = 0; j < 4; j++) {
            double s = 0.0;
            #pragma unroll
            for (int k = 0; k < 4; k++) s += A[i*4+k] * Bm[k*4+j];
            Cm[i*4+j] = s;
        }
}

// ---------------------------------------------------------------------------
// prep: 12 threads, each builds the fused transform for one (b, n)
// ---------------------------------------------------------------------------
__global__ void prep_kernel(const float* __restrict__ s2e,
                            const float* __restrict__ intrin,
                            const float* __restrict__ ida,
                            const float* __restrict__ bda) {
    int i = threadIdx.x;
    if (i >= BN_) return;
    int b = i / N_;
    double Mi[16], Ii[16], S[16], Bd[16], T[16], Cm[16];
    inv4x4d(intrin + i*16, Mi);
    inv4x4d(ida + i*16, Ii);
    #pragma unroll
    for (int k = 0; k < 16; k++) { S[k] = (double)s2e[i*16 + k]; Bd[k] = (double)bda[b*16 + k]; }
    mm4d(S, Mi, T);
    mm4d(Bd, T, Cm);
    #pragma unroll
    for (int k = 0; k < 16; k++) { g_comb[i][k] = (float)Cm[k]; g_idainv[i][k] = (float)Ii[k]; }
}

__global__ void zero_kernel(float* __restrict__ out, int n) {
    int i = blockIdx.x * blockDim.x + threadIdx.x;
    if (i < n) out[i] = 0.0f;
}

// ---------------------------------------------------------------------------
// main: one CTA (128 threads) per feature-map pixel (b, n, h, w)
//   softmax over D -> geometry/voxel per depth -> run-merge -> atomic scatter
// ---------------------------------------------------------------------------
__global__ __launch_bounds__(128) void lss_main(const float* __restrict__ ctx,
                                                const float* __restrict__ dl,
                                                float* __restrict__ out) {
    int pix = blockIdx.x;               // bn*704 + h*44 + w
    int bn  = pix / PIX_;
    int hw  = pix - bn * PIX_;
    int h   = hw / FW_;
    int w   = hw - h * FW_;
    int b   = bn / N_;
    int tid = threadIdx.x;

    __shared__ float sctx[C_];
    __shared__ float sw[D_];
    __shared__ int   slin[D_];
    __shared__ float red[128];
    __shared__ int   s_rlin[D_];
    __shared__ float s_rw[D_];
    __shared__ int   s_nr;

    if (tid < C_) sctx[tid] = ctx[(bn * C_ + tid) * PIX_ + hw];

    // ---- softmax over D=112 ----
    float l = -1e30f;
    if (tid < D_) l = dl[(bn * D_ + tid) * PIX_ + hw];
    red[tid] = l;
    __syncthreads();
    #pragma unroll
    for (int s = 64; s > 0; s >>= 1) {
        if (tid < s) red[tid] = fmaxf(red[tid], red[tid + s]);
        __syncthreads();
    }
    float mx = red[0];
    __syncthreads();
    float e = (tid < D_) ? expf(l - mx) : 0.0f;
    red[tid] = e;
    __syncthreads();
    #pragma unroll
    for (int s = 64; s > 0; s >>= 1) {
        if (tid < s) red[tid] += red[tid + s];
        __syncthreads();
    }
    float ssum = red[0];

    // ---- geometry & voxel index, one depth bin per thread ----
    if (tid < D_) {
        sw[tid] = e / ssum;
        float dd = 2.25f + 0.5f * (float)tid;            // exact
        float u  = (703.0f / 43.0f) * (float)w;          // linspace(0,703,44)
        float v  = (float)(17 * h);                      // linspace(0,255,16), exact
        const float* Ii = g_idainv[bn];
        float p0 = Ii[0]*u  + Ii[1]*v  + Ii[2]*dd  + Ii[3];
        float p1 = Ii[4]*u  + Ii[5]*v  + Ii[6]*dd  + Ii[7];
        float p2 = Ii[8]*u  + Ii[9]*v  + Ii[10]*dd + Ii[11];
        float p3 = Ii[12]*u + Ii[13]*v + Ii[14]*dd + Ii[15];
        float q0 = p0 * p2, q1 = p1 * p2, q2 = p2, q3 = p3;
        const float* Cm = g_comb[bn];
        float gx = Cm[0]*q0 + Cm[1]*q1 + Cm[2]*q2  + Cm[3]*q3;
        float gy = Cm[4]*q0 + Cm[5]*q1 + Cm[6]*q2  + Cm[7]*q3;
        float gz = Cm[8]*q0 + Cm[9]*q1 + Cm[10]*q2 + Cm[11]*q3;
        const float LO01 = -50.8f - 0.4f;   // vcoord - vsize/2 (f32, matches ref)
        const float LO2  = -1.0f  - 4.0f;
        int ix = (int)floorf(__fdiv_rn(gx - LO01, 0.8f));
        int iy = (int)floorf(__fdiv_rn(gy - LO01, 0.8f));
        int iz = (int)floorf(__fdiv_rn(gz - LO2,  8.0f));
        bool valid = (ix >= 0) && (ix < NX_) && (iy >= 0) && (iy < NY_) && (iz == 0);
        slin[tid] = valid ? (iy * NX_ + ix) : -1;
    }
    __syncthreads();

    // ---- run-length merge of consecutive depths in the same voxel ----
    if (tid == 0) {
        int nr = 0, prev = -1;
        for (int d = 0; d < D_; d++) {
            int li = slin[d];
            if (li < 0) { prev = -1; continue; }
            if (li == prev) {
                s_rw[nr - 1] += sw[d];
            } else {
                s_rlin[nr] = li; s_rw[nr] = sw[d]; nr++; prev = li;
            }
        }
        s_nr = nr;
    }
    __syncthreads();

    int nr = s_nr;
    if (nr == 0) return;

    // ---- scatter: nr runs x 80 channels; adjacent threads -> adjacent runs
    //      (adjacent voxels => good L2 atomic locality) ----
    float* outb = out + (size_t)b * (C_ * NX_ * NY_);
    int total = nr * C_;
    int c = tid / nr;
    int r = tid - c * nr;
    for (int p = tid; p < total; p += 128) {
        atomicAdd(outb + c * (NX_ * NY_) + s_rlin[r], s_rw[r] * sctx[c]);
        r += 128;
        while (r >= nr) { r -= nr; c++; }
    }
}

// ---------------------------------------------------------------------------
extern "C" void kernel_launch(void* const* d_in, const int* in_sizes, int n_in,
                              void* d_out, int out_size) {
    const float* ctx    = (const float*)d_in[0];
    const float* dl     = (const float*)d_in[1];
    const float* s2e    = (const float*)d_in[2];
    const float* intrin = (const float*)d_in[3];
    const float* ida    = (const float*)d_in[4];
    const float* bda    = (const float*)d_in[5];
    float* out = (float*)d_out;

    zero_kernel<<<(OUTN_ + 511) / 512, 512>>>(out, OUTN_);
    prep_kernel<<<1, 32>>>(s2e, intrin, ida, bda);
    lss_main<<<NPIX_, 128>>>(ctx, dl, out);
}

// round 2
// speedup vs baseline: 1.7731x; 1.7731x over previous
#include <cuda_runtime.h>
#include <math.h>

#define B_   2
#define N_   6
#define C_   80
#define FH_  16
#define FW_  44
#define D_   112
#define NX_  128
#define NY_  128
#define BN_  (B_*N_)
#define PIX_ (FH_*FW_)          // 704
#define NPIX_ (BN_*PIX_)        // 8448
#define CELLS_ (NX_*NY_)        // 16384
#define OUTN_ (B_*C_*CELLS_)    // 2621440

__device__ float g_comb[BN_][16];    // bda @ s2e @ inv(intrin)
__device__ float g_idainv[BN_][16];  // inv(ida)
__device__ __align__(128) float g_scratch[OUTN_];   // [B][Y*X][C] channel-last accumulator

// ---------------------------------------------------------------------------
// general 4x4 inverse (adjugate, double precision)
// ---------------------------------------------------------------------------
__device__ void inv4x4d(const float* src, double* out) {
    double m[16];
    #pragma unroll
    for (int i = 0; i < 16; i++) m[i] = (double)src[i];
    double inv[16];
    inv[0]  =  m[5]*m[10]*m[15] - m[5]*m[11]*m[14] - m[9]*m[6]*m[15] + m[9]*m[7]*m[14] + m[13]*m[6]*m[11] - m[13]*m[7]*m[10];
    inv[4]  = -m[4]*m[10]*m[15] + m[4]*m[11]*m[14] + m[8]*m[6]*m[15] - m[8]*m[7]*m[14] - m[12]*m[6]*m[11] + m[12]*m[7]*m[10];
    inv[8]  =  m[4]*m[9]*m[15]  - m[4]*m[11]*m[13] - m[8]*m[5]*m[15] + m[8]*m[7]*m[13] + m[12]*m[5]*m[11] - m[12]*m[7]*m[9];
    inv[12] = -m[4]*m[9]*m[14]  + m[4]*m[10]*m[13] + m[8]*m[5]*m[14] - m[8]*m[6]*m[13] - m[12]*m[5]*m[10] + m[12]*m[6]*m[9];
    inv[1]  = -m[1]*m[10]*m[15] + m[1]*m[11]*m[14] + m[9]*m[2]*m[15] - m[9]*m[3]*m[14] - m[13]*m[2]*m[11] + m[13]*m[3]*m[10];
    inv[5]  =  m[0]*m[10]*m[15] - m[0]*m[11]*m[14] - m[8]*m[2]*m[15] + m[8]*m[3]*m[14] + m[12]*m[2]*m[11] - m[12]*m[3]*m[10];
    inv[9]  = -m[0]*m[9]*m[15]  + m[0]*m[11]*m[13] + m[8]*m[1]*m[15] - m[8]*m[3]*m[13] - m[12]*m[1]*m[11] + m[12]*m[3]*m[9];
    inv[13] =  m[0]*m[9]*m[14]  - m[0]*m[10]*m[13] - m[8]*m[1]*m[14] + m[8]*m[2]*m[13] + m[12]*m[1]*m[10] - m[12]*m[2]*m[9];
    inv[2]  =  m[1]*m[6]*m[15]  - m[1]*m[7]*m[14]  - m[5]*m[2]*m[15] + m[5]*m[3]*m[14] + m[13]*m[2]*m[7]  - m[13]*m[3]*m[6];
    inv[6]  = -m[0]*m[6]*m[15]  + m[0]*m[7]*m[14]  + m[4]*m[2]*m[15] - m[4]*m[3]*m[14] - m[12]*m[2]*m[7]  + m[12]*m[3]*m[6];
    inv[10] =  m[0]*m[5]*m[15]  - m[0]*m[7]*m[13]  - m[4]*m[1]*m[15] + m[4]*m[3]*m[13] + m[12]*m[1]*m[7]  - m[12]*m[3]*m[5];
    inv[14] = -m[0]*m[5]*m[14]  + m[0]*m[6]*m[13]  + m[4]*m[1]*m[14] - m[4]*m[2]*m[13] - m[12]*m[1]*m[6]  + m[12]*m[2]*m[5];
    inv[3]  = -m[1]*m[6]*m[11]  + m[1]*m[7]*m[10]  + m[5]*m[2]*m[11] - m[5]*m[3]*m[10] - m[9]*m[2]*m[7]   + m[9]*m[3]*m[6];
    inv[7]  =  m[0]*m[6]*m[11]  - m[0]*m[7]*m[10]  - m[4]*m[2]*m[11] + m[4]*m[3]*m[10] + m[8]*m[2]*m[7]   - m[8]*m[3]*m[6];
    inv[11] = -m[0]*m[5]*m[11]  + m[0]*m[7]*m[9]   + m[4]*m[1]*m[11] - m[4]*m[3]*m[9]  - m[8]*m[1]*m[7]   + m[8]*m[3]*m[5];
    inv[15] =  m[0]*m[5]*m[10]  - m[0]*m[6]*m[9]   - m[4]*m[1]*m[10] + m[4]*m[2]*m[9]  + m[8]*m[1]*m[6]   - m[8]*m[2]*m[5];
    double det = m[0]*inv[0] + m[1]*inv[4] + m[2]*inv[8] + m[3]*inv[12];
    det = 1.0 / det;
    #pragma unroll
    for (int i = 0; i < 16; i++) out[i] = inv[i] * det;
}

__device__ void mm4d(const double* A, const double* Bm, double* Cm) {
    #pragma unroll
    for (int i = 0; i < 4; i++)
        #pragma unroll
        for (int j = 0; j < 4; j++) {
            double s = 0.0;
            #pragma unroll
            for (int k = 0; k < 4; k++) s += A[i*4+k] * Bm[k*4+j];
            Cm[i*4+j] = s;
        }
}

// ---------------------------------------------------------------------------
// prep: 12 threads, each builds the fused transform for one (b, n)
// ---------------------------------------------------------------------------
__global__ void prep_kernel(const float* __restrict__ s2e,
                            const float* __restrict__ intrin,
                            const float* __restrict__ ida,
                            const float* __restrict__ bda) {
    int i = threadIdx.x;
    if (i >= BN_) return;
    int b = i / N_;
    double Mi[16], Ii[16], S[16], Bd[16], T[16], Cm[16];
    inv4x4d(intrin + i*16, Mi);
    inv4x4d(ida + i*16, Ii);
    #pragma unroll
    for (int k = 0; k < 16; k++) { S[k] = (double)s2e[i*16 + k]; Bd[k] = (double)bda[b*16 + k]; }
    mm4d(S, Mi, T);
    mm4d(Bd, T, Cm);
    #pragma unroll
    for (int k = 0; k < 16; k++) { g_comb[i][k] = (float)Cm[k]; g_idainv[i][k] = (float)Ii[k]; }
}

// zero the channel-last scratch with float4 stores
__global__ __launch_bounds__(256) void zero_scratch_kernel() {
    int i = blockIdx.x * blockDim.x + threadIdx.x;
    ((float4*)g_scratch)[i] = make_float4(0.f, 0.f, 0.f, 0.f);
}

// ---------------------------------------------------------------------------
// main: one CTA (128 threads) per feature-map pixel (b, n, h, w)
//   softmax over D -> geometry/voxel per depth -> run-merge -> red.v4 scatter
// ---------------------------------------------------------------------------
__global__ __launch_bounds__(128) void lss_main(const float* __restrict__ ctx,
                                                const float* __restrict__ dl) {
    int pix = blockIdx.x;               // bn*704 + h*44 + w
    int bn  = pix / PIX_;
    int hw  = pix - bn * PIX_;
    int h   = hw / FW_;
    int w   = hw - h * FW_;
    int b   = bn / N_;
    int tid = threadIdx.x;

    __shared__ float sctx[C_];
    __shared__ float sw[D_];
    __shared__ int   slin[D_];
    __shared__ float red_[128];
    __shared__ int   s_rlin[D_];
    __shared__ float s_rw[D_];
    __shared__ int   s_nr;

    if (tid < C_) sctx[tid] = ctx[(bn * C_ + tid) * PIX_ + hw];

    // ---- softmax over D=112 ----
    float l = -1e30f;
    if (tid < D_) l = dl[(bn * D_ + tid) * PIX_ + hw];
    red_[tid] = l;
    __syncthreads();
    #pragma unroll
    for (int s = 64; s > 0; s >>= 1) {
        if (tid < s) red_[tid] = fmaxf(red_[tid], red_[tid + s]);
        __syncthreads();
    }
    float mx = red_[0];
    __syncthreads();
    float e = (tid < D_) ? expf(l - mx) : 0.0f;
    red_[tid] = e;
    __syncthreads();
    #pragma unroll
    for (int s = 64; s > 0; s >>= 1) {
        if (tid < s) red_[tid] += red_[tid + s];
        __syncthreads();
    }
    float ssum = red_[0];

    // ---- geometry & voxel index, one depth bin per thread ----
    if (tid < D_) {
        sw[tid] = e / ssum;
        float dd = 2.25f + 0.5f * (float)tid;            // exact
        float u  = (703.0f / 43.0f) * (float)w;          // linspace(0,703,44)
        float v  = (float)(17 * h);                      // linspace(0,255,16), exact
        const float* Ii = g_idainv[bn];
        float p0 = Ii[0]*u  + Ii[1]*v  + Ii[2]*dd  + Ii[3];
        float p1 = Ii[4]*u  + Ii[5]*v  + Ii[6]*dd  + Ii[7];
        float p2 = Ii[8]*u  + Ii[9]*v  + Ii[10]*dd + Ii[11];
        float p3 = Ii[12]*u + Ii[13]*v + Ii[14]*dd + Ii[15];
        float q0 = p0 * p2, q1 = p1 * p2, q2 = p2, q3 = p3;
        const float* Cm = g_comb[bn];
        float gx = Cm[0]*q0 + Cm[1]*q1 + Cm[2]*q2  + Cm[3]*q3;
        float gy = Cm[4]*q0 + Cm[5]*q1 + Cm[6]*q2  + Cm[7]*q3;
        float gz = Cm[8]*q0 + Cm[9]*q1 + Cm[10]*q2 + Cm[11]*q3;
        const float LO01 = -50.8f - 0.4f;   // vcoord - vsize/2 (f32, matches ref)
        const float LO2  = -1.0f  - 4.0f;
        int ix = (int)floorf(__fdiv_rn(gx - LO01, 0.8f));
        int iy = (int)floorf(__fdiv_rn(gy - LO01, 0.8f));
        int iz = (int)floorf(__fdiv_rn(gz - LO2,  8.0f));
        bool valid = (ix >= 0) && (ix < NX_) && (iy >= 0) && (iy < NY_) && (iz == 0);
        slin[tid] = valid ? (iy * NX_ + ix) : -1;
    }
    __syncthreads();

    // ---- run-length merge of consecutive depths in the same voxel ----
    if (tid == 0) {
        int nr = 0, prev = -1;
        for (int d = 0; d < D_; d++) {
            int li = slin[d];
            if (li < 0) { prev = -1; continue; }
            if (li == prev) {
                s_rw[nr - 1] += sw[d];
            } else {
                s_rlin[nr] = li; s_rw[nr] = sw[d]; nr++; prev = li;
            }
        }
        s_nr = nr;
    }
    __syncthreads();

    int nr = s_nr;
    if (nr == 0) return;

    // ---- scatter: nr runs x 20 float4 quads into channel-last scratch.
    //      Adjacent threads take consecutive quads of the same run ->
    //      one warp covers a contiguous 320B region (good L2 sector packing).
    float* sbase = g_scratch + (size_t)b * (CELLS_ * C_);
    int total = nr * (C_ / 4);
    for (int p = tid; p < total; p += 128) {
        int r  = p / (C_ / 4);
        int q4 = p - r * (C_ / 4);
        float wgt = s_rw[r];
        float v0 = wgt * sctx[q4*4 + 0];
        float v1 = wgt * sctx[q4*4 + 1];
        float v2 = wgt * sctx[q4*4 + 2];
        float v3 = wgt * sctx[q4*4 + 3];
        float* addr = sbase + (size_t)s_rlin[r] * C_ + q4 * 4;
        asm volatile("red.global.add.v4.f32 [%0], {%1, %2, %3, %4};"
                     :: "l"(addr), "f"(v0), "f"(v1), "f"(v2), "f"(v3)
                     : "memory");
    }
}

// ---------------------------------------------------------------------------
// transpose: [B][Y*X][C] scratch -> [B][C][Y*X] output (writes ALL elements)
// ---------------------------------------------------------------------------
__global__ __launch_bounds__(256) void transpose_kernel(float* __restrict__ out) {
    __shared__ float tile[64][C_ + 1];
    int b   = blockIdx.y;
    int yx0 = blockIdx.x * 64;
    const float4* s4 = (const float4*)(g_scratch + ((size_t)b * CELLS_ + yx0) * C_);
    // load 64 cells x 80 ch = 1280 float4
    for (int p = threadIdx.x; p < 64 * (C_ / 4); p += 256) {
        int cell = p / (C_ / 4);
        int q    = p - cell * (C_ / 4);
        float4 v = s4[cell * (C_ / 4) + q];
        tile[cell][q*4+0] = v.x; tile[cell][q*4+1] = v.y;
        tile[cell][q*4+2] = v.z; tile[cell][q*4+3] = v.w;
    }
    __syncthreads();
    float* ob = out + (size_t)b * C_ * CELLS_ + yx0;
    for (int p = threadIdx.x; p < 64 * C_; p += 256) {
        int c = p / 64;
        int i = p - c * 64;
        ob[(size_t)c * CELLS_ + i] = tile[i][c];
    }
}

// ---------------------------------------------------------------------------
extern "C" void kernel_launch(void* const* d_in, const int* in_sizes, int n_in,
                              void* d_out, int out_size) {
    const float* ctx    = (const float*)d_in[0];
    const float* dl     = (const float*)d_in[1];
    const float* s2e    = (const float*)d_in[2];
    const float* intrin = (const float*)d_in[3];
    const float* ida    = (const float*)d_in[4];
    const float* bda    = (const float*)d_in[5];
    float* out = (float*)d_out;

    zero_scratch_kernel<<<OUTN_ / 4 / 256, 256>>>();
    prep_kernel<<<1, 32>>>(s2e, intrin, ida, bda);
    lss_main<<<NPIX_, 128>>>(ctx, dl);
    transpose_kernel<<<dim3(CELLS_ / 64, B_), 256>>>(out);
}